// round 3
// baseline (speedup 1.0000x reference)
#include <cuda_runtime.h>

#define L_NODES 100000
#define NFEAT   256
#define JDIM    128
#define NSAMP   8

// Scratch (static __device__ arrays; no allocation allowed)
__device__ float g_H [(size_t)L_NODES * JDIM];        // H = relu(X@W_h1+b)        (L,128)
__device__ float g_AB[(size_t)L_NODES * 2 * JDIM];    // [A|B] = H@[Wtop|Wbot]     (L,256); reused as E2 (L,128)
__device__ float g_E [(size_t)L_NODES * JDIM];        // E = mean_s relu(A[i0]+B[i1]+bg)

// ---------------------------------------------------------------------------
// Generic tiled SGEMM, N fixed at 128 per launch. C = op(Acat @ W + bias)
// Acat: logical (M, K) where cols [0,Ksplit) come from A1, [Ksplit,K) from A2
// (both row-major with stride lda). W: row-major (K, 128), row stride 128.
// Block tile 128x128, BK=16, 256 threads, 8x8 micro-tile per thread.
// ---------------------------------------------------------------------------
__global__ __launch_bounds__(256) void sgemm_bn128(
    const float* __restrict__ A1, const float* __restrict__ A2,
    int Ksplit, int K, int lda,
    const float* __restrict__ W,
    const float* __restrict__ bias,   // may be null
    float* __restrict__ C, int ldc,
    int M, int do_relu)
{
    __shared__ float As[16][128];
    __shared__ float Ws[16][128];

    const int tid     = threadIdx.x;
    const int warp_id = tid >> 5;
    const int lane    = tid & 31;
    // warp layout: 4x2 warps over 128x128; lane layout 4x8 within 32x64 warp tile
    const int row0  = (warp_id >> 1) * 32 + (lane >> 3) * 8;
    const int col0  = (warp_id & 1) * 64 + (lane & 7) * 8;
    const int mbase = blockIdx.x * 128;

    float acc[8][8];
#pragma unroll
    for (int i = 0; i < 8; i++)
#pragma unroll
        for (int j = 0; j < 8; j++) acc[i][j] = 0.f;

    for (int k0 = 0; k0 < K; k0 += 16) {
        const float* Aptr;
        int kloc;
        if (k0 < Ksplit) { Aptr = A1; kloc = k0; }
        else             { Aptr = A2; kloc = k0 - Ksplit; }

        // Load A tile: 128 rows x 16 k  (512 float4, 2 per thread), store transposed
#pragma unroll
        for (int i = 0; i < 2; i++) {
            int f  = tid + i * 256;           // 0..511
            int r  = f >> 2;                  // 0..127
            int kq = (f & 3) << 2;            // 0,4,8,12
            int grow = mbase + r;
            float4 v = make_float4(0.f, 0.f, 0.f, 0.f);
            if (grow < M)
                v = *(const float4*)(Aptr + (size_t)grow * lda + kloc + kq);
            As[kq + 0][r] = v.x;
            As[kq + 1][r] = v.y;
            As[kq + 2][r] = v.z;
            As[kq + 3][r] = v.w;
        }
        // Load W tile: 16 k x 128 n
#pragma unroll
        for (int i = 0; i < 2; i++) {
            int f  = tid + i * 256;
            int kk = f >> 5;                  // 0..15
            int nq = (f & 31) << 2;           // 0..124
            *(float4*)&Ws[kk][nq] =
                *(const float4*)(W + (size_t)(k0 + kk) * 128 + nq);
        }
        __syncthreads();

#pragma unroll
        for (int kk = 0; kk < 16; kk++) {
            float4 a0 = *(const float4*)&As[kk][row0];
            float4 a1 = *(const float4*)&As[kk][row0 + 4];
            float4 b0 = *(const float4*)&Ws[kk][col0];
            float4 b1 = *(const float4*)&Ws[kk][col0 + 4];
            float ra[8] = {a0.x, a0.y, a0.z, a0.w, a1.x, a1.y, a1.z, a1.w};
            float rb[8] = {b0.x, b0.y, b0.z, b0.w, b1.x, b1.y, b1.z, b1.w};
#pragma unroll
            for (int i = 0; i < 8; i++)
#pragma unroll
                for (int j = 0; j < 8; j++)
                    acc[i][j] = fmaf(ra[i], rb[j], acc[i][j]);
        }
        __syncthreads();
    }

    float bv[8];
#pragma unroll
    for (int j = 0; j < 8; j++) bv[j] = bias ? bias[col0 + j] : 0.f;

#pragma unroll
    for (int i = 0; i < 8; i++) {
        int grow = mbase + row0 + i;
        if (grow >= M) continue;
        float vals[8];
#pragma unroll
        for (int j = 0; j < 8; j++) {
            float v = acc[i][j] + bv[j];
            if (do_relu) v = fmaxf(v, 0.f);
            vals[j] = v;
        }
        *(float4*)(C + (size_t)grow * ldc + col0) =
            make_float4(vals[0], vals[1], vals[2], vals[3]);
        *(float4*)(C + (size_t)grow * ldc + col0 + 4) =
            make_float4(vals[4], vals[5], vals[6], vals[7]);
    }
}

// ---------------------------------------------------------------------------
// K3: E[l, :] = (1/S) * sum_s relu(A[idx0[s,l], :] + B[idx1[s,l], :] + b_g1)
// One warp per row l; lane owns 4 consecutive floats (float4).
// AB viewed as float4: row = 64 float4 (A = [0,32), B = [32,64)).
// ---------------------------------------------------------------------------
__global__ __launch_bounds__(256) void gather_mean_kernel(
    const float4* __restrict__ AB,
    const int* __restrict__ idx0, const int* __restrict__ idx1,
    const float* __restrict__ bg,
    float4* __restrict__ E)
{
    int gw   = (blockIdx.x * blockDim.x + threadIdx.x) >> 5;  // row
    int lane = threadIdx.x & 31;
    if (gw >= L_NODES) return;

    float4 bg4 = ((const float4*)bg)[lane];
    float4 acc = make_float4(0.f, 0.f, 0.f, 0.f);
#pragma unroll
    for (int s = 0; s < NSAMP; s++) {
        int i0 = idx0[s * L_NODES + gw];
        int i1 = idx1[s * L_NODES + gw];
        float4 a = AB[(size_t)i0 * 64 + lane];
        float4 b = AB[(size_t)i1 * 64 + 32 + lane];
        acc.x += fmaxf(a.x + b.x + bg4.x, 0.f);
        acc.y += fmaxf(a.y + b.y + bg4.y, 0.f);
        acc.z += fmaxf(a.z + b.z + bg4.z, 0.f);
        acc.w += fmaxf(a.w + b.w + bg4.w, 0.f);
    }
    const float inv = 1.0f / (float)NSAMP;
    E[(size_t)gw * 32 + lane] =
        make_float4(acc.x * inv, acc.y * inv, acc.z * inv, acc.w * inv);
}

// ---------------------------------------------------------------------------
// K5: out[l, :] = E2[l, :] @ W_f + b_f   (W_f: 128x2 row-major)
// One warp per row; lane loads float4 of E2, warp-reduce two dot products.
// ---------------------------------------------------------------------------
__global__ __launch_bounds__(256) void final_kernel(
    const float* __restrict__ E2,
    const float* __restrict__ Wf, const float* __restrict__ bf,
    float* __restrict__ out)
{
    int gw   = (blockIdx.x * blockDim.x + threadIdx.x) >> 5;
    int lane = threadIdx.x & 31;
    if (gw >= L_NODES) return;

    float4 e = *(const float4*)(E2 + (size_t)gw * 128 + lane * 4);
    float a0 = 0.f, a1 = 0.f;
    const float* ev = &e.x;
#pragma unroll
    for (int j = 0; j < 4; j++) {
        int k = lane * 4 + j;
        a0 = fmaf(ev[j], Wf[k * 2 + 0], a0);
        a1 = fmaf(ev[j], Wf[k * 2 + 1], a1);
    }
#pragma unroll
    for (int o = 16; o > 0; o >>= 1) {
        a0 += __shfl_xor_sync(0xffffffffu, a0, o);
        a1 += __shfl_xor_sync(0xffffffffu, a1, o);
    }
    if (lane == 0) {
        out[(size_t)gw * 2 + 0] = a0 + bf[0];
        out[(size_t)gw * 2 + 1] = a1 + bf[1];
    }
}

extern "C" void kernel_launch(void* const* d_in, const int* in_sizes, int n_in,
                              void* d_out, int out_size)
{
    const float* X    = (const float*)d_in[0];
    const float* W_h1 = (const float*)d_in[1];
    const float* b_h1 = (const float*)d_in[2];
    const float* W_g1 = (const float*)d_in[3];   // (256, 128) row-major
    const float* b_g1 = (const float*)d_in[4];
    const float* W_f  = (const float*)d_in[5];
    const float* b_f  = (const float*)d_in[6];
    const int*   idx0 = (const int*)d_in[7];     // (8, 100000)
    const int*   idx1 = (const int*)d_in[8];
    float* out = (float*)d_out;

    float *H, *AB, *E;
    cudaGetSymbolAddress((void**)&H,  g_H);
    cudaGetSymbolAddress((void**)&AB, g_AB);
    cudaGetSymbolAddress((void**)&E,  g_E);

    const int MT = (L_NODES + 127) / 128;  // 782 row tiles
    const int GW = (L_NODES * 32) / 256;   // 12500 blocks (exact)

    // K1: H = relu(X @ W_h1 + b_h1)
    sgemm_bn128<<<MT, 256>>>(X, X, 256, 256, 256, W_h1, b_h1, H, 128, L_NODES, 1);
    // K2a: A = H @ W_g1[0:128,:]  -> AB[:, 0:128]
    sgemm_bn128<<<MT, 256>>>(H, H, 128, 128, 128, W_g1, nullptr, AB, 256, L_NODES, 0);
    // K2b: B = H @ W_g1[128:256,:] -> AB[:, 128:256]
    sgemm_bn128<<<MT, 256>>>(H, H, 128, 128, 128, W_g1 + 128 * 128, nullptr,
                             AB + 128, 256, L_NODES, 0);
    // K3: E = mean_s relu(A[idx0] + B[idx1] + b_g1)  (outer relu is identity)
    gather_mean_kernel<<<GW, 256>>>((const float4*)AB, idx0, idx1, b_g1, (float4*)E);
    // K4: E2 = relu(H @ Wtop + E @ Wbot + b_g1); reuse AB as E2 (ldc=128)
    sgemm_bn128<<<MT, 256>>>(H, E, 128, 256, 128, W_g1, b_g1, AB, 128, L_NODES, 1);
    // K5: out = E2 @ W_f + b_f
    final_kernel<<<GW, 256>>>(AB, W_f, b_f, out);
}

// round 5
// speedup vs baseline: 1.0507x; 1.0507x over previous
#include <cuda_runtime.h>
#include <cstdint>

#define L_NODES 100000
#define NFEAT   256
#define JDIM    128
#define NSAMP   8

// Scratch (static __device__ arrays; no allocation allowed)
__device__ float g_H [(size_t)L_NODES * JDIM];        // H = relu(X@W_h1+b)        (L,128)
__device__ float g_AB[(size_t)L_NODES * 2 * JDIM];    // [A|B] = H@[Wtop|Wbot]     (L,256); reused as E2
__device__ float g_E [(size_t)L_NODES * JDIM];        // E = mean_s relu(A[i0]+B[i1]+bg)

// ---------------------------------------------------------------------------
// tf32 helpers
// ---------------------------------------------------------------------------
__device__ __forceinline__ uint32_t f2tf32(float x) {
    uint32_t r;
    asm("cvt.rna.tf32.f32 %0, %1;" : "=r"(r) : "f"(x));
    return r;
}

__device__ __forceinline__ void mma_tf32(float c[4], const uint32_t a[4],
                                         const uint32_t b[2]) {
    asm volatile(
        "mma.sync.aligned.m16n8k8.row.col.f32.tf32.tf32.f32 "
        "{%0,%1,%2,%3}, {%4,%5,%6,%7}, {%8,%9}, {%0,%1,%2,%3};"
        : "+f"(c[0]), "+f"(c[1]), "+f"(c[2]), "+f"(c[3])
        : "r"(a[0]), "r"(a[1]), "r"(a[2]), "r"(a[3]), "r"(b[0]), "r"(b[1]));
}

// XOR swizzle for the A tile: makes BOTH the transposed store (lanes vary in
// k bits 2-3) and the fragment load (lanes vary in k bits 0-1) conflict-free
// with a plain stride-128 layout.
#define ASWZ(k, r) ((r) ^ (((((k) >> 2) ^ (k)) & 3) << 3))

// ---------------------------------------------------------------------------
// Tensor-core GEMM (3xTF32), N fixed at 128. C = op(Acat @ W + bias)
// Acat: logical (M, K); cols [0,Ksplit) from A1, [Ksplit,K) from A2 (row-major,
// stride lda). W row-major (K, 128). Block tile 128x128, BK=16, 256 threads.
// 8 warps in a 4(m) x 2(n) grid; warp tile 32x64 = 2 x 8 m16n8k8 tiles.
// Accuracy: A = Ahi + Alo, W = Whi + Wlo (tf32 split); acc += Ahi*Whi +
// Ahi*Wlo + Alo*Whi  (Alo*Wlo ~2^-24, dropped) -> fp32-class error.
// ---------------------------------------------------------------------------
__global__ __launch_bounds__(256) void tgemm_bn128(
    const float* __restrict__ A1, const float* __restrict__ A2,
    int Ksplit, int K, int lda,
    const float* __restrict__ W,
    const float* __restrict__ bias,   // may be null
    float* __restrict__ C, int ldc,
    int M, int do_relu)
{
    __shared__ float As_hi[16][128];
    __shared__ float As_lo[16][128];
    __shared__ float Ws_hi[16][136];
    __shared__ float Ws_lo[16][136];

    const int tid  = threadIdx.x;
    const int wid  = tid >> 5;
    const int lane = tid & 31;
    const int wm   = wid >> 1;        // 0..3
    const int wn   = wid & 1;         // 0..1
    const int t    = lane & 3;        // quad column (k within 4)
    const int q    = lane >> 2;       // quad row
    const int mbase = blockIdx.x * 128;

    float acc[2][8][4];
#pragma unroll
    for (int i = 0; i < 2; i++)
#pragma unroll
        for (int j = 0; j < 8; j++)
#pragma unroll
            for (int v = 0; v < 4; v++) acc[i][j][v] = 0.f;

    for (int k0 = 0; k0 < K; k0 += 16) {
        const float* Aptr;
        int kloc;
        if (k0 < Ksplit) { Aptr = A1; kloc = k0; }
        else             { Aptr = A2; kloc = k0 - Ksplit; }

        // ---- A tile: 128 rows x 16 k, split to hi/lo, stored transposed ----
#pragma unroll
        for (int i = 0; i < 2; i++) {
            int f  = tid + i * 256;            // 0..511 float4 slots
            int r  = f >> 2;                   // 0..127 (row)
            int kq = (f & 3) << 2;             // 0,4,8,12
            int grow = mbase + r;
            float4 v = make_float4(0.f, 0.f, 0.f, 0.f);
            if (grow < M)
                v = *(const float4*)(Aptr + (size_t)grow * lda + kloc + kq);
            float xs[4] = {v.x, v.y, v.z, v.w};
#pragma unroll
            for (int j = 0; j < 4; j++) {
                int k = kq + j;
                float hi = __uint_as_float(f2tf32(xs[j]));
                As_hi[k][ASWZ(k, r)] = hi;
                As_lo[k][ASWZ(k, r)] = xs[j] - hi;
            }
        }
        // ---- W tile: 16 k x 128 n, split hi/lo, STS.128 ----
#pragma unroll
        for (int i = 0; i < 2; i++) {
            int f  = tid + i * 256;
            int kk = f >> 5;                   // 0..15
            int nq = (f & 31) << 2;            // 0..124
            float4 v = *(const float4*)(W + (size_t)(k0 + kk) * 128 + nq);
            float4 hi4, lo4;
            hi4.x = __uint_as_float(f2tf32(v.x)); lo4.x = v.x - hi4.x;
            hi4.y = __uint_as_float(f2tf32(v.y)); lo4.y = v.y - hi4.y;
            hi4.z = __uint_as_float(f2tf32(v.z)); lo4.z = v.z - hi4.z;
            hi4.w = __uint_as_float(f2tf32(v.w)); lo4.w = v.w - hi4.w;
            *(float4*)&Ws_hi[kk][nq] = hi4;
            *(float4*)&Ws_lo[kk][nq] = lo4;
        }
        __syncthreads();

#pragma unroll
        for (int ks = 0; ks < 2; ks++) {
            const int kb = ks * 8;
            // A fragments (2 m-tiles), hi + lo
            uint32_t ah[2][4], al[2][4];
#pragma unroll
            for (int mt = 0; mt < 2; mt++) {
                int row = wm * 32 + mt * 16 + q;
                int ka = kb + t, kc = kb + t + 4;
                ah[mt][0] = __float_as_uint(As_hi[ka][ASWZ(ka, row)]);
                ah[mt][1] = __float_as_uint(As_hi[ka][ASWZ(ka, row + 8)]);
                ah[mt][2] = __float_as_uint(As_hi[kc][ASWZ(kc, row)]);
                ah[mt][3] = __float_as_uint(As_hi[kc][ASWZ(kc, row + 8)]);
                al[mt][0] = __float_as_uint(As_lo[ka][ASWZ(ka, row)]);
                al[mt][1] = __float_as_uint(As_lo[ka][ASWZ(ka, row + 8)]);
                al[mt][2] = __float_as_uint(As_lo[kc][ASWZ(kc, row)]);
                al[mt][3] = __float_as_uint(As_lo[kc][ASWZ(kc, row + 8)]);
            }
            // B fragments in 2 groups of 4 n-tiles (register pressure)
#pragma unroll
            for (int g = 0; g < 2; g++) {
                uint32_t bh[4][2], bl[4][2];
#pragma unroll
                for (int j = 0; j < 4; j++) {
                    int col = wn * 64 + (g * 4 + j) * 8 + q;
                    bh[j][0] = __float_as_uint(Ws_hi[kb + t][col]);
                    bh[j][1] = __float_as_uint(Ws_hi[kb + t + 4][col]);
                    bl[j][0] = __float_as_uint(Ws_lo[kb + t][col]);
                    bl[j][1] = __float_as_uint(Ws_lo[kb + t + 4][col]);
                }
#pragma unroll
                for (int mt = 0; mt < 2; mt++)
#pragma unroll
                    for (int j = 0; j < 4; j++) {
                        float* c = acc[mt][g * 4 + j];
                        mma_tf32(c, ah[mt], bh[j]);   // hi*hi (main)
                        mma_tf32(c, ah[mt], bl[j]);   // hi*lo (corr)
                        mma_tf32(c, al[mt], bh[j]);   // lo*hi (corr)
                    }
            }
        }
        __syncthreads();
    }

    // ---- epilogue: bias + optional relu, float2 stores ----
#pragma unroll
    for (int mt = 0; mt < 2; mt++) {
#pragma unroll
        for (int nt = 0; nt < 8; nt++) {
            int row = mbase + wm * 32 + mt * 16 + q;
            int col = wn * 64 + nt * 8 + 2 * t;
            float b0 = bias ? bias[col]     : 0.f;
            float b1 = bias ? bias[col + 1] : 0.f;
            float v0 = acc[mt][nt][0] + b0;
            float v1 = acc[mt][nt][1] + b1;
            float v2 = acc[mt][nt][2] + b0;
            float v3 = acc[mt][nt][3] + b1;
            if (do_relu) {
                v0 = fmaxf(v0, 0.f); v1 = fmaxf(v1, 0.f);
                v2 = fmaxf(v2, 0.f); v3 = fmaxf(v3, 0.f);
            }
            if (row < M)
                *(float2*)(C + (size_t)row * ldc + col) = make_float2(v0, v1);
            if (row + 8 < M)
                *(float2*)(C + (size_t)(row + 8) * ldc + col) = make_float2(v2, v3);
        }
    }
}

// ---------------------------------------------------------------------------
// K3: E[l, :] = (1/S) * sum_s relu(A[idx0[s,l], :] + B[idx1[s,l], :] + b_g1)
// One warp per row l; lane owns a float4. AB row = 64 float4 (A=[0,32), B=[32,64)).
// ---------------------------------------------------------------------------
__global__ __launch_bounds__(256) void gather_mean_kernel(
    const float4* __restrict__ AB,
    const int* __restrict__ idx0, const int* __restrict__ idx1,
    const float* __restrict__ bg,
    float4* __restrict__ E)
{
    int gw   = (blockIdx.x * blockDim.x + threadIdx.x) >> 5;  // row
    int lane = threadIdx.x & 31;
    if (gw >= L_NODES) return;

    float4 bg4 = ((const float4*)bg)[lane];
    float4 acc = make_float4(0.f, 0.f, 0.f, 0.f);
#pragma unroll
    for (int s = 0; s < NSAMP; s++) {
        int i0 = idx0[s * L_NODES + gw];
        int i1 = idx1[s * L_NODES + gw];
        float4 a = AB[(size_t)i0 * 64 + lane];
        float4 b = AB[(size_t)i1 * 64 + 32 + lane];
        acc.x += fmaxf(a.x + b.x + bg4.x, 0.f);
        acc.y += fmaxf(a.y + b.y + bg4.y, 0.f);
        acc.z += fmaxf(a.z + b.z + bg4.z, 0.f);
        acc.w += fmaxf(a.w + b.w + bg4.w, 0.f);
    }
    const float inv = 1.0f / (float)NSAMP;
    E[(size_t)gw * 32 + lane] =
        make_float4(acc.x * inv, acc.y * inv, acc.z * inv, acc.w * inv);
}

// ---------------------------------------------------------------------------
// K5: out[l, :] = E2[l, :] @ W_f + b_f   (W_f: 128x2 row-major)
// ---------------------------------------------------------------------------
__global__ __launch_bounds__(256) void final_kernel(
    const float* __restrict__ E2,
    const float* __restrict__ Wf, const float* __restrict__ bf,
    float* __restrict__ out)
{
    int gw   = (blockIdx.x * blockDim.x + threadIdx.x) >> 5;
    int lane = threadIdx.x & 31;
    if (gw >= L_NODES) return;

    float4 e = *(const float4*)(E2 + (size_t)gw * 128 + lane * 4);
    float a0 = 0.f, a1 = 0.f;
    const float* ev = &e.x;
#pragma unroll
    for (int j = 0; j < 4; j++) {
        int k = lane * 4 + j;
        a0 = fmaf(ev[j], Wf[k * 2 + 0], a0);
        a1 = fmaf(ev[j], Wf[k * 2 + 1], a1);
    }
#pragma unroll
    for (int o = 16; o > 0; o >>= 1) {
        a0 += __shfl_xor_sync(0xffffffffu, a0, o);
        a1 += __shfl_xor_sync(0xffffffffu, a1, o);
    }
    if (lane == 0) {
        out[(size_t)gw * 2 + 0] = a0 + bf[0];
        out[(size_t)gw * 2 + 1] = a1 + bf[1];
    }
}

extern "C" void kernel_launch(void* const* d_in, const int* in_sizes, int n_in,
                              void* d_out, int out_size)
{
    const float* X    = (const float*)d_in[0];
    const float* W_h1 = (const float*)d_in[1];
    const float* b_h1 = (const float*)d_in[2];
    const float* W_g1 = (const float*)d_in[3];   // (256, 128) row-major
    const float* b_g1 = (const float*)d_in[4];
    const float* W_f  = (const float*)d_in[5];
    const float* b_f  = (const float*)d_in[6];
    const int*   idx0 = (const int*)d_in[7];     // (8, 100000)
    const int*   idx1 = (const int*)d_in[8];
    float* out = (float*)d_out;

    float *H, *AB, *E;
    cudaGetSymbolAddress((void**)&H,  g_H);
    cudaGetSymbolAddress((void**)&AB, g_AB);
    cudaGetSymbolAddress((void**)&E,  g_E);

    const int MT = (L_NODES + 127) / 128;  // 782 row tiles
    const int GW = (L_NODES * 32) / 256;   // 12500 blocks (exact)

    // K1: H = relu(X @ W_h1 + b_h1)
    tgemm_bn128<<<MT, 256>>>(X, X, 256, 256, 256, W_h1, b_h1, H, 128, L_NODES, 1);
    // K2a: A = H @ W_g1[0:128,:]  -> AB[:, 0:128]
    tgemm_bn128<<<MT, 256>>>(H, H, 128, 128, 128, W_g1, nullptr, AB, 256, L_NODES, 0);
    // K2b: B = H @ W_g1[128:256,:] -> AB[:, 128:256]
    tgemm_bn128<<<MT, 256>>>(H, H, 128, 128, 128, W_g1 + 128 * 128, nullptr,
                             AB + 128, 256, L_NODES, 0);
    // K3: E = mean_s relu(A[idx0] + B[idx1] + b_g1)  (outer relu is identity)
    gather_mean_kernel<<<GW, 256>>>((const float4*)AB, idx0, idx1, b_g1, (float4*)E);
    // K4: E2 = relu(H @ Wtop + E @ Wbot + b_g1); reuse AB as E2 (ldc=128)
    tgemm_bn128<<<MT, 256>>>(H, E, 128, 256, 128, W_g1, b_g1, AB, 128, L_NODES, 1);
    // K5: out = E2 @ W_f + b_f
    final_kernel<<<GW, 256>>>(AB, W_f, b_f, out);
}

// round 10
// speedup vs baseline: 1.7377x; 1.6538x over previous
#include <cuda_runtime.h>
#include <cuda_bf16.h>
#include <cstdint>

#define L_NODES 100000
#define NFEAT   256
#define JDIM    128
#define NSAMP   8

// Scratch (static __device__ arrays; no allocation allowed)
__device__ float g_H [(size_t)L_NODES * JDIM];
__device__ float g_AB[(size_t)L_NODES * 2 * JDIM];   // [A|B]; later reused as E2
__device__ float g_E [(size_t)L_NODES * JDIM];

// ---------------------------------------------------------------------------
// bf16 helpers
// ---------------------------------------------------------------------------
__device__ __forceinline__ unsigned short bfh(float x) {
    return __bfloat16_as_ushort(__float2bfloat16(x));
}
__device__ __forceinline__ float bff(unsigned short u) {
    return __bfloat162float(__ushort_as_bfloat16(u));
}
__device__ __forceinline__ uint32_t pack2(unsigned short a, unsigned short b) {
    return (uint32_t)a | ((uint32_t)b << 16);
}

__device__ __forceinline__ void mma_bf16(float c[4], const uint32_t a[4],
                                         const uint32_t b[2]) {
    asm volatile(
        "mma.sync.aligned.m16n8k16.row.col.f32.bf16.bf16.f32 "
        "{%0,%1,%2,%3}, {%4,%5,%6,%7}, {%8,%9}, {%0,%1,%2,%3};"
        : "+f"(c[0]), "+f"(c[1]), "+f"(c[2]), "+f"(c[3])
        : "r"(a[0]), "r"(a[1]), "r"(a[2]), "r"(a[3]), "r"(b[0]), "r"(b[1]));
}

// A-tile swizzle: bank = (row-bits) xor (kp<<3) -> all 32 lanes of a fragment
// load hit distinct banks.
#define ASWZ(kp, r) ((r) ^ (((kp) & 3) << 3))

// ---------------------------------------------------------------------------
// Tensor-core GEMM (3x bf16 hi/lo), N fixed at 128. C = op(Acat @ W + bias)
// Acat: logical (M, K); cols [0,Ksplit) from A1, [Ksplit,K) from A2 (row-major,
// stride lda). W row-major (K, 128). Block tile 128x128, BK=16, 256 threads.
// 8 warps in a 4(m) x 2(n) grid; warp tile 32x64 = 2 x 8 m16n8k16 tiles.
// A = Ahi + Alo, W = Whi + Wlo (bf16 split); acc += Ahi*Whi + Ahi*Wlo + Alo*Whi
// (Alo*Wlo ~2^-32 rel, dropped). fp32 accumulate in HMMA.
// Smem layout (uint32 = packed bf16 pair along k):
//   As[8 kpair][128 row]  (swizzled)     Ws[8 kpair][136 col] (padded)
// ---------------------------------------------------------------------------
__global__ __launch_bounds__(256) void bgemm_bn128(
    const float* __restrict__ A1, const float* __restrict__ A2,
    int Ksplit, int K, int lda,
    const float* __restrict__ W,
    const float* __restrict__ bias,   // may be null
    float* __restrict__ C, int ldc,
    int M, int do_relu)
{
    __shared__ uint32_t As_hi[8][128];
    __shared__ uint32_t As_lo[8][128];
    __shared__ uint32_t Ws_hi[8][136];
    __shared__ uint32_t Ws_lo[8][136];

    const int tid  = threadIdx.x;
    const int wid  = tid >> 5;
    const int lane = tid & 31;
    const int wm   = wid >> 1;        // 0..3
    const int wn   = wid & 1;         // 0..1
    const int t    = lane & 3;        // quad column
    const int q    = lane >> 2;       // quad row
    const int mbase = blockIdx.x * 128;

    float acc[2][8][4];
#pragma unroll
    for (int i = 0; i < 2; i++)
#pragma unroll
        for (int j = 0; j < 8; j++)
#pragma unroll
            for (int v = 0; v < 4; v++) acc[i][j][v] = 0.f;

    for (int k0 = 0; k0 < K; k0 += 16) {
        const float* Aptr;
        int kloc;
        if (k0 < Ksplit) { Aptr = A1; kloc = k0; }
        else             { Aptr = A2; kloc = k0 - Ksplit; }

        // ---- A tile: 128 rows x 16 k -> bf16 hi/lo pairs, transposed ----
#pragma unroll
        for (int i = 0; i < 2; i++) {
            int f  = tid + i * 256;            // 0..511 float4 slots
            int r  = f >> 2;                   // 0..127 (row)
            int kq = (f & 3) << 2;             // k = kq..kq+3 -> kpairs kq/2, kq/2+1
            int grow = mbase + r;
            float4 v = make_float4(0.f, 0.f, 0.f, 0.f);
            if (grow < M)
                v = *(const float4*)(Aptr + (size_t)grow * lda + kloc + kq);
            unsigned short hx = bfh(v.x), hy = bfh(v.y), hz = bfh(v.z), hw = bfh(v.w);
            int p0 = kq >> 1, p1 = p0 + 1;
            As_hi[p0][ASWZ(p0, r)] = pack2(hx, hy);
            As_hi[p1][ASWZ(p1, r)] = pack2(hz, hw);
            As_lo[p0][ASWZ(p0, r)] = pack2(bfh(v.x - bff(hx)), bfh(v.y - bff(hy)));
            As_lo[p1][ASWZ(p1, r)] = pack2(bfh(v.z - bff(hz)), bfh(v.w - bff(hw)));
        }
        // ---- W tile: 16 k x 128 n -> bf16 hi/lo pairs (k-pair packed) ----
        {
            int kp = tid >> 5;                 // 0..7
            int nq = (tid & 31) << 2;          // 0..124
            const float* w0 = W + (size_t)(k0 + 2 * kp)     * 128 + nq;
            const float* w1 = W + (size_t)(k0 + 2 * kp + 1) * 128 + nq;
            float4 a = *(const float4*)w0;
            float4 b = *(const float4*)w1;
            const float* av = &a.x;
            const float* bv = &b.x;
#pragma unroll
            for (int j = 0; j < 4; j++) {
                unsigned short ha = bfh(av[j]), hb = bfh(bv[j]);
                Ws_hi[kp][nq + j] = pack2(ha, hb);
                Ws_lo[kp][nq + j] = pack2(bfh(av[j] - bff(ha)), bfh(bv[j] - bff(hb)));
            }
        }
        __syncthreads();

        // ---- fragments + MMAs (one k16 step) ----
        uint32_t ah[2][4], al[2][4];
#pragma unroll
        for (int mt = 0; mt < 2; mt++) {
            int row = wm * 32 + mt * 16 + q;
            int pa = t, pb = t + 4;
            ah[mt][0] = As_hi[pa][ASWZ(pa, row)];
            ah[mt][1] = As_hi[pa][ASWZ(pa, row + 8)];
            ah[mt][2] = As_hi[pb][ASWZ(pb, row)];
            ah[mt][3] = As_hi[pb][ASWZ(pb, row + 8)];
            al[mt][0] = As_lo[pa][ASWZ(pa, row)];
            al[mt][1] = As_lo[pa][ASWZ(pa, row + 8)];
            al[mt][2] = As_lo[pb][ASWZ(pb, row)];
            al[mt][3] = As_lo[pb][ASWZ(pb, row + 8)];
        }
#pragma unroll
        for (int g = 0; g < 2; g++) {
            uint32_t bh[4][2], bl[4][2];
#pragma unroll
            for (int j = 0; j < 4; j++) {
                int col = wn * 64 + (g * 4 + j) * 8 + q;
                bh[j][0] = Ws_hi[t][col];
                bh[j][1] = Ws_hi[t + 4][col];
                bl[j][0] = Ws_lo[t][col];
                bl[j][1] = Ws_lo[t + 4][col];
            }
#pragma unroll
            for (int mt = 0; mt < 2; mt++)
#pragma unroll
                for (int j = 0; j < 4; j++) {
                    float* c = acc[mt][g * 4 + j];
                    mma_bf16(c, ah[mt], bh[j]);   // hi*hi (main)
                    mma_bf16(c, ah[mt], bl[j]);   // hi*lo (corr)
                    mma_bf16(c, al[mt], bh[j]);   // lo*hi (corr)
                }
        }
        __syncthreads();
    }

    // ---- epilogue: bias + optional relu, float2 stores ----
#pragma unroll
    for (int mt = 0; mt < 2; mt++) {
#pragma unroll
        for (int nt = 0; nt < 8; nt++) {
            int row = mbase + wm * 32 + mt * 16 + q;
            int col = wn * 64 + nt * 8 + 2 * t;
            float b0 = bias ? bias[col]     : 0.f;
            float b1 = bias ? bias[col + 1] : 0.f;
            float v0 = acc[mt][nt][0] + b0;
            float v1 = acc[mt][nt][1] + b1;
            float v2 = acc[mt][nt][2] + b0;
            float v3 = acc[mt][nt][3] + b1;
            if (do_relu) {
                v0 = fmaxf(v0, 0.f); v1 = fmaxf(v1, 0.f);
                v2 = fmaxf(v2, 0.f); v3 = fmaxf(v3, 0.f);
            }
            if (row < M)
                *(float2*)(C + (size_t)row * ldc + col) = make_float2(v0, v1);
            if (row + 8 < M)
                *(float2*)(C + (size_t)(row + 8) * ldc + col) = make_float2(v2, v3);
        }
    }
}

// ---------------------------------------------------------------------------
// K3: E[l,:] = (1/S) * sum_s relu(A[idx0[s,l],:] + B[idx1[s,l],:] + b_g1)
// One warp per row l; lane owns a float4. AB row = 64 float4 (A=[0,32), B=[32,64)).
// ---------------------------------------------------------------------------
__global__ __launch_bounds__(256) void gather_mean_kernel(
    const float4* __restrict__ AB,
    const int* __restrict__ idx0, const int* __restrict__ idx1,
    const float* __restrict__ bg,
    float4* __restrict__ E)
{
    int gw   = (blockIdx.x * blockDim.x + threadIdx.x) >> 5;
    int lane = threadIdx.x & 31;
    if (gw >= L_NODES) return;

    float4 bg4 = ((const float4*)bg)[lane];
    float4 acc = make_float4(0.f, 0.f, 0.f, 0.f);
#pragma unroll
    for (int s = 0; s < NSAMP; s++) {
        int i0 = idx0[s * L_NODES + gw];
        int i1 = idx1[s * L_NODES + gw];
        float4 a = AB[(size_t)i0 * 64 + lane];
        float4 b = AB[(size_t)i1 * 64 + 32 + lane];
        acc.x += fmaxf(a.x + b.x + bg4.x, 0.f);
        acc.y += fmaxf(a.y + b.y + bg4.y, 0.f);
        acc.z += fmaxf(a.z + b.z + bg4.z, 0.f);
        acc.w += fmaxf(a.w + b.w + bg4.w, 0.f);
    }
    const float inv = 1.0f / (float)NSAMP;
    E[(size_t)gw * 32 + lane] =
        make_float4(acc.x * inv, acc.y * inv, acc.z * inv, acc.w * inv);
}

// ---------------------------------------------------------------------------
// K5: out[l,:] = E2[l,:] @ W_f + b_f   (W_f: 128x2 row-major)
// ---------------------------------------------------------------------------
__global__ __launch_bounds__(256) void final_kernel(
    const float* __restrict__ E2,
    const float* __restrict__ Wf, const float* __restrict__ bf,
    float* __restrict__ out)
{
    int gw   = (blockIdx.x * blockDim.x + threadIdx.x) >> 5;
    int lane = threadIdx.x & 31;
    if (gw >= L_NODES) return;

    float4 e = *(const float4*)(E2 + (size_t)gw * 128 + lane * 4);
    float a0 = 0.f, a1 = 0.f;
    const float* ev = &e.x;
#pragma unroll
    for (int j = 0; j < 4; j++) {
        int k = lane * 4 + j;
        a0 = fmaf(ev[j], Wf[k * 2 + 0], a0);
        a1 = fmaf(ev[j], Wf[k * 2 + 1], a1);
    }
#pragma unroll
    for (int o = 16; o > 0; o >>= 1) {
        a0 += __shfl_xor_sync(0xffffffffu, a0, o);
        a1 += __shfl_xor_sync(0xffffffffu, a1, o);
    }
    if (lane == 0) {
        out[(size_t)gw * 2 + 0] = a0 + bf[0];
        out[(size_t)gw * 2 + 1] = a1 + bf[1];
    }
}

extern "C" void kernel_launch(void* const* d_in, const int* in_sizes, int n_in,
                              void* d_out, int out_size)
{
    const float* X    = (const float*)d_in[0];
    const float* W_h1 = (const float*)d_in[1];
    const float* b_h1 = (const float*)d_in[2];
    const float* W_g1 = (const float*)d_in[3];   // (256, 128) row-major
    const float* b_g1 = (const float*)d_in[4];
    const float* W_f  = (const float*)d_in[5];
    const float* b_f  = (const float*)d_in[6];
    const int*   idx0 = (const int*)d_in[7];     // (8, 100000)
    const int*   idx1 = (const int*)d_in[8];
    float* out = (float*)d_out;

    float *H, *AB, *E;
    cudaGetSymbolAddress((void**)&H,  g_H);
    cudaGetSymbolAddress((void**)&AB, g_AB);
    cudaGetSymbolAddress((void**)&E,  g_E);

    const int MT = (L_NODES + 127) / 128;  // 782 row tiles
    const int GW = (L_NODES * 32) / 256;   // 12500 blocks (exact)

    // K1: H = relu(X @ W_h1 + b_h1)
    bgemm_bn128<<<MT, 256>>>(X, X, 256, 256, 256, W_h1, b_h1, H, 128, L_NODES, 1);
    // K2a: A = H @ W_g1[0:128,:]  -> AB[:, 0:128]
    bgemm_bn128<<<MT, 256>>>(H, H, 128, 128, 128, W_g1, nullptr, AB, 256, L_NODES, 0);
    // K2b: B = H @ W_g1[128:256,:] -> AB[:, 128:256]
    bgemm_bn128<<<MT, 256>>>(H, H, 128, 128, 128, W_g1 + 128 * 128, nullptr,
                             AB + 128, 256, L_NODES, 0);
    // K3: E = mean_s relu(A[idx0] + B[idx1] + b_g1)  (outer relu is identity)
    gather_mean_kernel<<<GW, 256>>>((const float4*)AB, idx0, idx1, b_g1, (float4*)E);
    // K4: E2 = relu(H @ Wtop + E @ Wbot + b_g1); reuse AB as E2 (ldc=128)
    bgemm_bn128<<<MT, 256>>>(H, E, 128, 256, 128, W_g1, b_g1, AB, 128, L_NODES, 1);
    // K5: out = E2 @ W_f + b_f
    final_kernel<<<GW, 256>>>(AB, W_f, b_f, out);
}

// round 11
// speedup vs baseline: 1.8750x; 1.0790x over previous
#include <cuda_runtime.h>
#include <cuda_bf16.h>
#include <cstdint>

#define L_NODES 100000
#define NFEAT   256
#define JDIM    128
#define NSAMP   8

// Scratch (static __device__ arrays; no allocation allowed)
__device__ float g_H [(size_t)L_NODES * JDIM];
__device__ float g_AB[(size_t)L_NODES * 2 * JDIM];   // [A|B]
__device__ float g_E [(size_t)L_NODES * JDIM];

// ---------------------------------------------------------------------------
// bf16 helpers
// ---------------------------------------------------------------------------
__device__ __forceinline__ unsigned short bfh(float x) {
    return __bfloat16_as_ushort(__float2bfloat16(x));
}
__device__ __forceinline__ float bff(unsigned short u) {
    return __bfloat162float(__ushort_as_bfloat16(u));
}
__device__ __forceinline__ uint32_t pack2(unsigned short a, unsigned short b) {
    return (uint32_t)a | ((uint32_t)b << 16);
}

__device__ __forceinline__ void mma_bf16(float c[4], const uint32_t a[4],
                                         const uint32_t b[2]) {
    asm volatile(
        "mma.sync.aligned.m16n8k16.row.col.f32.bf16.bf16.f32 "
        "{%0,%1,%2,%3}, {%4,%5,%6,%7}, {%8,%9}, {%0,%1,%2,%3};"
        : "+f"(c[0]), "+f"(c[1]), "+f"(c[2]), "+f"(c[3])
        : "r"(a[0]), "r"(a[1]), "r"(a[2]), "r"(a[3]), "r"(b[0]), "r"(b[1]));
}

// A-tile swizzle: bank = (row-bits) xor (kp<<3)
#define ASWZ(kp, r) ((r) ^ (((kp) & 3) << 3))

// ---------------------------------------------------------------------------
// Tensor-core GEMM (3x bf16 hi/lo), N=128. C = op(Acat @ W + bias).
// If Wf != null: fused final layer — out[row,0:2] = op(...) @ Wf + bf2,
// and C is NOT written.
// Register-prefetch pipeline: chunk c+1's global loads issue before chunk c's
// MMA block, hiding global latency under tensor issue.
// ---------------------------------------------------------------------------
__global__ __launch_bounds__(256, 2) void bgemm_bn128(
    const float* __restrict__ A1, const float* __restrict__ A2,
    int Ksplit, int K, int lda,
    const float* __restrict__ W,
    const float* __restrict__ bias,   // may be null
    float* __restrict__ C, int ldc,
    int M, int do_relu,
    const float* __restrict__ Wf,     // 128x2, or null
    const float* __restrict__ bf2,
    float* __restrict__ outp)
{
    __shared__ uint32_t As_hi[8][128];
    __shared__ uint32_t As_lo[8][128];
    __shared__ uint32_t Ws_hi[8][136];
    __shared__ uint32_t Ws_lo[8][136];

    const int tid  = threadIdx.x;
    const int wid  = tid >> 5;
    const int lane = tid & 31;
    const int wm   = wid >> 1;        // 0..3
    const int wn   = wid & 1;         // 0..1
    const int t    = lane & 3;        // quad column
    const int q    = lane >> 2;       // quad row
    const int mbase = blockIdx.x * 128;

    // A-load geometry (fixed across chunks): 2 float4 per thread
    const int ar0 = tid >> 2;                 // row for slot 0 (0..63)
    const int ar1 = (tid + 256) >> 2;         // row for slot 1 (64..127)
    const int akq = (tid & 3) << 2;           // k offset 0,4,8,12
    // W-load geometry
    const int wkp = tid >> 5;                 // 0..7
    const int wnq = (tid & 31) << 2;          // 0..124

    float acc[2][8][4];
#pragma unroll
    for (int i = 0; i < 2; i++)
#pragma unroll
        for (int j = 0; j < 8; j++)
#pragma unroll
            for (int v = 0; v < 4; v++) acc[i][j][v] = 0.f;

    const int nchunks = K >> 4;

    // ---- prologue: prefetch chunk 0 ----
    float4 pa0, pa1, pw0, pw1;
    {
        const float* Aptr = (0 < Ksplit) ? A1 : A2;
        int kloc = (0 < Ksplit) ? 0 : -Ksplit;
        pa0 = make_float4(0.f, 0.f, 0.f, 0.f);
        pa1 = make_float4(0.f, 0.f, 0.f, 0.f);
        if (mbase + ar0 < M)
            pa0 = *(const float4*)(Aptr + (size_t)(mbase + ar0) * lda + kloc + akq);
        if (mbase + ar1 < M)
            pa1 = *(const float4*)(Aptr + (size_t)(mbase + ar1) * lda + kloc + akq);
        pw0 = *(const float4*)(W + (size_t)(2 * wkp)     * 128 + wnq);
        pw1 = *(const float4*)(W + (size_t)(2 * wkp + 1) * 128 + wnq);
    }

    for (int c = 0; c < nchunks; c++) {
        // ---- convert prefetched regs -> smem (prev MMAs done: sync at loop end) ----
        {
            // A slot 0
            float4 v = pa0;
            unsigned short hx = bfh(v.x), hy = bfh(v.y), hz = bfh(v.z), hw = bfh(v.w);
            int p0 = akq >> 1, p1 = p0 + 1;
            As_hi[p0][ASWZ(p0, ar0)] = pack2(hx, hy);
            As_hi[p1][ASWZ(p1, ar0)] = pack2(hz, hw);
            As_lo[p0][ASWZ(p0, ar0)] = pack2(bfh(v.x - bff(hx)), bfh(v.y - bff(hy)));
            As_lo[p1][ASWZ(p1, ar0)] = pack2(bfh(v.z - bff(hz)), bfh(v.w - bff(hw)));
            // A slot 1
            v = pa1;
            hx = bfh(v.x); hy = bfh(v.y); hz = bfh(v.z); hw = bfh(v.w);
            As_hi[p0][ASWZ(p0, ar1)] = pack2(hx, hy);
            As_hi[p1][ASWZ(p1, ar1)] = pack2(hz, hw);
            As_lo[p0][ASWZ(p0, ar1)] = pack2(bfh(v.x - bff(hx)), bfh(v.y - bff(hy)));
            As_lo[p1][ASWZ(p1, ar1)] = pack2(bfh(v.z - bff(hz)), bfh(v.w - bff(hw)));
            // W
            const float* av = &pw0.x;
            const float* bv = &pw1.x;
#pragma unroll
            for (int j = 0; j < 4; j++) {
                unsigned short ha = bfh(av[j]), hb = bfh(bv[j]);
                Ws_hi[wkp][wnq + j] = pack2(ha, hb);
                Ws_lo[wkp][wnq + j] = pack2(bfh(av[j] - bff(ha)), bfh(bv[j] - bff(hb)));
            }
        }
        __syncthreads();

        // ---- prefetch chunk c+1 (latency hides under MMAs below) ----
        if (c + 1 < nchunks) {
            int k0 = (c + 1) << 4;
            const float* Aptr = (k0 < Ksplit) ? A1 : A2;
            int kloc = (k0 < Ksplit) ? k0 : k0 - Ksplit;
            pa0 = make_float4(0.f, 0.f, 0.f, 0.f);
            pa1 = make_float4(0.f, 0.f, 0.f, 0.f);
            if (mbase + ar0 < M)
                pa0 = *(const float4*)(Aptr + (size_t)(mbase + ar0) * lda + kloc + akq);
            if (mbase + ar1 < M)
                pa1 = *(const float4*)(Aptr + (size_t)(mbase + ar1) * lda + kloc + akq);
            pw0 = *(const float4*)(W + (size_t)(k0 + 2 * wkp)     * 128 + wnq);
            pw1 = *(const float4*)(W + (size_t)(k0 + 2 * wkp + 1) * 128 + wnq);
        }

        // ---- fragments + MMAs (one k16 step) ----
        uint32_t ah[2][4], al[2][4];
#pragma unroll
        for (int mt = 0; mt < 2; mt++) {
            int row = wm * 32 + mt * 16 + q;
            int pa = t, pb = t + 4;
            ah[mt][0] = As_hi[pa][ASWZ(pa, row)];
            ah[mt][1] = As_hi[pa][ASWZ(pa, row + 8)];
            ah[mt][2] = As_hi[pb][ASWZ(pb, row)];
            ah[mt][3] = As_hi[pb][ASWZ(pb, row + 8)];
            al[mt][0] = As_lo[pa][ASWZ(pa, row)];
            al[mt][1] = As_lo[pa][ASWZ(pa, row + 8)];
            al[mt][2] = As_lo[pb][ASWZ(pb, row)];
            al[mt][3] = As_lo[pb][ASWZ(pb, row + 8)];
        }
#pragma unroll
        for (int g = 0; g < 2; g++) {
            uint32_t bh[4][2], bl[4][2];
#pragma unroll
            for (int j = 0; j < 4; j++) {
                int col = wn * 64 + (g * 4 + j) * 8 + q;
                bh[j][0] = Ws_hi[t][col];
                bh[j][1] = Ws_hi[t + 4][col];
                bl[j][0] = Ws_lo[t][col];
                bl[j][1] = Ws_lo[t + 4][col];
            }
#pragma unroll
            for (int mt = 0; mt < 2; mt++)
#pragma unroll
                for (int j = 0; j < 4; j++) {
                    float* cc = acc[mt][g * 4 + j];
                    mma_bf16(cc, ah[mt], bh[j]);   // hi*hi
                    mma_bf16(cc, ah[mt], bl[j]);   // hi*lo
                    mma_bf16(cc, al[mt], bh[j]);   // lo*hi
                }
        }
        __syncthreads();
    }

    if (!Wf) {
        // ---- epilogue: bias + optional relu, float2 stores ----
#pragma unroll
        for (int mt = 0; mt < 2; mt++) {
#pragma unroll
            for (int nt = 0; nt < 8; nt++) {
                int row = mbase + wm * 32 + mt * 16 + q;
                int col = wn * 64 + nt * 8 + 2 * t;
                float b0 = bias ? bias[col]     : 0.f;
                float b1 = bias ? bias[col + 1] : 0.f;
                float v0 = acc[mt][nt][0] + b0;
                float v1 = acc[mt][nt][1] + b1;
                float v2 = acc[mt][nt][2] + b0;
                float v3 = acc[mt][nt][3] + b1;
                if (do_relu) {
                    v0 = fmaxf(v0, 0.f); v1 = fmaxf(v1, 0.f);
                    v2 = fmaxf(v2, 0.f); v3 = fmaxf(v3, 0.f);
                }
                if (row < M)
                    *(float2*)(C + (size_t)row * ldc + col) = make_float2(v0, v1);
                if (row + 8 < M)
                    *(float2*)(C + (size_t)(row + 8) * ldc + col) = make_float2(v2, v3);
            }
        }
    } else {
        // ---- fused final layer: out = relu(acc + bias) @ Wf + bf2 ----
        __shared__ float red[2][128][2];          // [wn][row][out]
        float p[2][2][2];                         // [mt][rowhalf][out]
#pragma unroll
        for (int mt = 0; mt < 2; mt++)
#pragma unroll
            for (int h = 0; h < 2; h++) { p[mt][h][0] = 0.f; p[mt][h][1] = 0.f; }

#pragma unroll
        for (int nt = 0; nt < 8; nt++) {
            int col = wn * 64 + nt * 8 + 2 * t;
            float b0 = bias ? bias[col]     : 0.f;
            float b1 = bias ? bias[col + 1] : 0.f;
            float w00 = Wf[col * 2 + 0], w01 = Wf[col * 2 + 1];
            float w10 = Wf[col * 2 + 2], w11 = Wf[col * 2 + 3];
#pragma unroll
            for (int mt = 0; mt < 2; mt++) {
                float e0 = acc[mt][nt][0] + b0;
                float e1 = acc[mt][nt][1] + b1;
                float e2 = acc[mt][nt][2] + b0;
                float e3 = acc[mt][nt][3] + b1;
                if (do_relu) {
                    e0 = fmaxf(e0, 0.f); e1 = fmaxf(e1, 0.f);
                    e2 = fmaxf(e2, 0.f); e3 = fmaxf(e3, 0.f);
                }
                p[mt][0][0] = fmaf(e0, w00, fmaf(e1, w10, p[mt][0][0]));
                p[mt][0][1] = fmaf(e0, w01, fmaf(e1, w11, p[mt][0][1]));
                p[mt][1][0] = fmaf(e2, w00, fmaf(e3, w10, p[mt][1][0]));
                p[mt][1][1] = fmaf(e2, w01, fmaf(e3, w11, p[mt][1][1]));
            }
        }
        // reduce over the 4 t-lanes (lanes q*4 + t; xor 1 and 2 stay in-group)
#pragma unroll
        for (int mt = 0; mt < 2; mt++)
#pragma unroll
            for (int h = 0; h < 2; h++)
#pragma unroll
                for (int o = 0; o < 2; o++) {
                    float v = p[mt][h][o];
                    v += __shfl_xor_sync(0xffffffffu, v, 1);
                    v += __shfl_xor_sync(0xffffffffu, v, 2);
                    p[mt][h][o] = v;
                }
        if (t == 0) {
#pragma unroll
            for (int mt = 0; mt < 2; mt++)
#pragma unroll
                for (int h = 0; h < 2; h++) {
                    int row = wm * 32 + mt * 16 + q + h * 8;
                    red[wn][row][0] = p[mt][h][0];
                    red[wn][row][1] = p[mt][h][1];
                }
        }
        __syncthreads();
        {
            int row = tid >> 1, o = tid & 1;
            int grow = mbase + row;
            if (grow < M)
                outp[(size_t)grow * 2 + o] =
                    red[0][row][o] + red[1][row][o] + bf2[o];
        }
    }
}

// ---------------------------------------------------------------------------
// K3: E[l,:] = (1/S) * sum_s relu(A[idx0[s,l],:] + B[idx1[s,l],:] + b_g1)
// ---------------------------------------------------------------------------
__global__ __launch_bounds__(256) void gather_mean_kernel(
    const float4* __restrict__ AB,
    const int* __restrict__ idx0, const int* __restrict__ idx1,
    const float* __restrict__ bg,
    float4* __restrict__ E)
{
    int gw   = (blockIdx.x * blockDim.x + threadIdx.x) >> 5;
    int lane = threadIdx.x & 31;
    if (gw >= L_NODES) return;

    float4 bg4 = ((const float4*)bg)[lane];
    float4 acc = make_float4(0.f, 0.f, 0.f, 0.f);
#pragma unroll
    for (int s = 0; s < NSAMP; s++) {
        int i0 = idx0[s * L_NODES + gw];
        int i1 = idx1[s * L_NODES + gw];
        float4 a = AB[(size_t)i0 * 64 + lane];
        float4 b = AB[(size_t)i1 * 64 + 32 + lane];
        acc.x += fmaxf(a.x + b.x + bg4.x, 0.f);
        acc.y += fmaxf(a.y + b.y + bg4.y, 0.f);
        acc.z += fmaxf(a.z + b.z + bg4.z, 0.f);
        acc.w += fmaxf(a.w + b.w + bg4.w, 0.f);
    }
    const float inv = 1.0f / (float)NSAMP;
    E[(size_t)gw * 32 + lane] =
        make_float4(acc.x * inv, acc.y * inv, acc.z * inv, acc.w * inv);
}

extern "C" void kernel_launch(void* const* d_in, const int* in_sizes, int n_in,
                              void* d_out, int out_size)
{
    const float* X    = (const float*)d_in[0];
    const float* W_h1 = (const float*)d_in[1];
    const float* b_h1 = (const float*)d_in[2];
    const float* W_g1 = (const float*)d_in[3];   // (256, 128) row-major
    const float* b_g1 = (const float*)d_in[4];
    const float* W_f  = (const float*)d_in[5];
    const float* b_f  = (const float*)d_in[6];
    const int*   idx0 = (const int*)d_in[7];     // (8, 100000)
    const int*   idx1 = (const int*)d_in[8];
    float* out = (float*)d_out;

    float *H, *AB, *E;
    cudaGetSymbolAddress((void**)&H,  g_H);
    cudaGetSymbolAddress((void**)&AB, g_AB);
    cudaGetSymbolAddress((void**)&E,  g_E);

    const int MT = (L_NODES + 127) / 128;  // 782 row tiles
    const int GW = (L_NODES * 32) / 256;   // 12500 blocks (exact)

    // K1: H = relu(X @ W_h1 + b_h1)
    bgemm_bn128<<<MT, 256>>>(X, X, 256, 256, 256, W_h1, b_h1, H, 128, L_NODES, 1,
                             nullptr, nullptr, nullptr);
    // K2a: A = H @ W_g1[0:128,:]  -> AB[:, 0:128]
    bgemm_bn128<<<MT, 256>>>(H, H, 128, 128, 128, W_g1, nullptr, AB, 256, L_NODES, 0,
                             nullptr, nullptr, nullptr);
    // K2b: B = H @ W_g1[128:256,:] -> AB[:, 128:256]
    bgemm_bn128<<<MT, 256>>>(H, H, 128, 128, 128, W_g1 + 128 * 128, nullptr,
                             AB + 128, 256, L_NODES, 0,
                             nullptr, nullptr, nullptr);
    // K3: E = mean_s relu(A[idx0] + B[idx1] + b_g1)  (outer relu is identity)
    gather_mean_kernel<<<GW, 256>>>((const float4*)AB, idx0, idx1, b_g1, (float4*)E);
    // K4+K5 fused: out = relu([H|E] @ W_g1 + b_g1) @ W_f + b_f
    bgemm_bn128<<<MT, 256>>>(H, E, 128, 256, 128, W_g1, b_g1, AB, 128, L_NODES, 1,
                             W_f, b_f, out);
}